// round 11
// baseline (speedup 1.0000x reference)
#include <cuda_runtime.h>
#include <cuda_bf16.h>
#include <cstdint>

// Problem constants
#define B_  8
#define N_  1024
#define C_  256
#define H_  8
#define BH_ (B_ * H_)
#define HEAD_ELEMS_ 524288
#define SCALE_ 0.0625f

// Scratch (device globals)
__device__ float g_q[BH_ * N_ * 64];
__device__ float g_k[BH_ * N_ * 64];
__device__ float g_part[2048];
__device__ float g_stats[16 * 2];
__device__ int   g_ticket;
__device__ __nv_bfloat16 g_qh[BH_ * N_ * 64];
__device__ __nv_bfloat16 g_ql[BH_ * N_ * 64];
__device__ __nv_bfloat16 g_kh[BH_ * N_ * 64];
__device__ __nv_bfloat16 g_kl[BH_ * N_ * 64];
__device__ __nv_bfloat16 g_xh[8192 * 256];
__device__ __nv_bfloat16 g_xl[8192 * 256];
__device__ __nv_bfloat16 g_wh[1024 * 256];
__device__ __nv_bfloat16 g_wl[1024 * 256];
__device__ float g_scores[(size_t)BH_ * N_ * N_];   // S^T[b,h,m,n] 256 MB

// ---------------------------------------------------------------------------
// helpers
// ---------------------------------------------------------------------------
__device__ __forceinline__ uint32_t smem_u32(const void* p) {
    uint32_t a;
    asm("{ .reg .u64 t; cvta.to.shared.u64 t, %1; cvt.u32.u64 %0, t; }" : "=r"(a) : "l"(p));
    return a;
}
__device__ __forceinline__ void ldsm_x4(uint32_t* r, uint32_t addr) {
    asm volatile("ldmatrix.sync.aligned.m8n8.x4.shared.b16 {%0,%1,%2,%3}, [%4];"
                 : "=r"(r[0]), "=r"(r[1]), "=r"(r[2]), "=r"(r[3]) : "r"(addr));
}
__device__ __forceinline__ void mma_bf16(float* c, const uint32_t* a, uint32_t b0, uint32_t b1) {
    asm volatile("mma.sync.aligned.m16n8k16.row.col.f32.bf16.bf16.f32 "
                 "{%0,%1,%2,%3},{%4,%5,%6,%7},{%8,%9},{%0,%1,%2,%3};"
                 : "+f"(c[0]), "+f"(c[1]), "+f"(c[2]), "+f"(c[3])
                 : "r"(a[0]), "r"(a[1]), "r"(a[2]), "r"(a[3]), "r"(b0), "r"(b1));
}
__device__ __forceinline__ void cp16(uint32_t d, const void* s) {
    asm volatile("cp.async.cg.shared.global [%0], [%1], 16;" :: "r"(d), "l"(s));
}
#define CP_COMMIT() asm volatile("cp.async.commit_group;" ::: "memory")
#define CP_WAIT1()  asm volatile("cp.async.wait_group 1;" ::: "memory")
#define CP_WAIT0()  asm volatile("cp.async.wait_group 0;" ::: "memory")

// ---------------------------------------------------------------------------
// Kernel 0: bf16 hi/lo split of x and [qw;kw]
// ---------------------------------------------------------------------------
__global__ void __launch_bounds__(256) split_inputs_kernel(const float* __restrict__ x,
                                                           const float* __restrict__ qw,
                                                           const float* __restrict__ kw) {
    int idx = (blockIdx.x * 256 + threadIdx.x) * 4;
    const float* src;
    __nv_bfloat16 *dh, *dl;
    int off;
    if (idx < 2097152) {
        src = x; off = idx; dh = g_xh; dl = g_xl;
    } else if (idx < 2097152 + 131072) {
        src = qw; off = idx - 2097152; dh = g_wh; dl = g_wl;
    } else {
        src = kw; off = idx - 2097152 - 131072; dh = g_wh + 131072; dl = g_wl + 131072;
    }
    float4 v = *(const float4*)(src + off);
    __nv_bfloat16 h0 = __float2bfloat16(v.x), h1 = __float2bfloat16(v.y);
    __nv_bfloat16 h2 = __float2bfloat16(v.z), h3 = __float2bfloat16(v.w);
    __nv_bfloat162 hv0, hv1, lv0, lv1;
    hv0.x = h0; hv0.y = h1; hv1.x = h2; hv1.y = h3;
    lv0.x = __float2bfloat16(v.x - __bfloat162float(h0));
    lv0.y = __float2bfloat16(v.y - __bfloat162float(h1));
    lv1.x = __float2bfloat16(v.z - __bfloat162float(h2));
    lv1.y = __float2bfloat16(v.w - __bfloat162float(h3));
    *(__nv_bfloat162*)(dh + off)     = hv0;
    *(__nv_bfloat162*)(dh + off + 2) = hv1;
    *(__nv_bfloat162*)(dl + off)     = lv0;
    *(__nv_bfloat162*)(dl + off + 2) = lv1;
}

// ---------------------------------------------------------------------------
// Kernel 1: q/k = x @ w^T, cp.async 2-stage pipeline over 8 k-chunks of 32.
// Epilogue folds BN partial stats; last CTA (ticket) finalizes g_stats.
// ---------------------------------------------------------------------------
#define QK_STAGE 40960
#define QK_AHI 0
#define QK_ALO 10240
#define QK_BHI 20480
#define QK_BLO 30720
#define QK_SMEM (2 * QK_STAGE)   // 81920

__global__ void __launch_bounds__(256, 2) gemm_qk_mma() {
    extern __shared__ char smq[];
    const uint32_t sb = smem_u32(smq);
    const int tid = threadIdx.x;
    const int wid = tid >> 5, lane = tid & 31;
    const int bx = blockIdx.x, by = blockIdx.y, bz = blockIdx.z;
    const int m0 = by * 128, n0 = bx * 128;
    const __nv_bfloat16* Bh = g_wh + (size_t)(bz * 512) * 256;
    const __nv_bfloat16* Bl = g_wl + (size_t)(bz * 512) * 256;

    auto stage = [&](int kc, int buf) {
        uint32_t base = sb + buf * QK_STAGE;
#pragma unroll
        for (int i = 0; i < 2; i++) {
            int idx = tid + i * 256;
            int row = idx >> 2, c = idx & 3;
            uint32_t so = (uint32_t)row * 80 + c * 16;
            size_t goA = (size_t)(m0 + row) * 256 + kc * 32 + c * 8;
            size_t goB = (size_t)(n0 + row) * 256 + kc * 32 + c * 8;
            cp16(base + QK_AHI + so, g_xh + goA);
            cp16(base + QK_ALO + so, g_xl + goA);
            cp16(base + QK_BHI + so, Bh + goB);
            cp16(base + QK_BLO + so, Bl + goB);
        }
    };

    const int wm = (wid & 3) * 32;
    const int wn = (wid >> 2) * 64;
    const int l07 = lane & 7;
    const int b3 = (lane >> 3) & 1;
    const int b4 = lane >> 4;
    const uint32_t aOff = (uint32_t)(wm + b3 * 8 + l07) * 80 + b4 * 16;
    const uint32_t bOff = (uint32_t)(wn + b4 * 8 + l07) * 80 + b3 * 16;

    float acc[2][8][4];
#pragma unroll
    for (int f = 0; f < 2; f++)
#pragma unroll
        for (int g = 0; g < 8; g++)
#pragma unroll
            for (int j = 0; j < 4; j++) acc[f][g][j] = 0.f;

    stage(0, 0);
    CP_COMMIT();

#pragma unroll 1
    for (int kc = 0; kc < 8; kc++) {
        if (kc < 7) { stage(kc + 1, (kc + 1) & 1); CP_COMMIT(); CP_WAIT1(); }
        else CP_WAIT0();
        __syncthreads();
        uint32_t base = sb + (kc & 1) * QK_STAGE;
#pragma unroll
        for (int ks = 0; ks < 2; ks++) {
            uint32_t ah[2][4], al[2][4];
#pragma unroll
            for (int f = 0; f < 2; f++) {
                ldsm_x4(ah[f], base + QK_AHI + aOff + f * 1280 + ks * 32);
                ldsm_x4(al[f], base + QK_ALO + aOff + f * 1280 + ks * 32);
            }
            uint32_t bhf[4][4], blf[4][4];
#pragma unroll
            for (int p = 0; p < 4; p++) {
                ldsm_x4(bhf[p], base + QK_BHI + bOff + p * 1280 + ks * 32);
                ldsm_x4(blf[p], base + QK_BLO + bOff + p * 1280 + ks * 32);
            }
#pragma unroll
            for (int f = 0; f < 2; f++)
#pragma unroll
                for (int p = 0; p < 4; p++) {
                    mma_bf16(acc[f][2 * p],     ah[f], bhf[p][0], bhf[p][1]);
                    mma_bf16(acc[f][2 * p],     al[f], bhf[p][0], bhf[p][1]);
                    mma_bf16(acc[f][2 * p],     ah[f], blf[p][0], blf[p][1]);
                    mma_bf16(acc[f][2 * p + 1], ah[f], bhf[p][2], bhf[p][3]);
                    mma_bf16(acc[f][2 * p + 1], al[f], bhf[p][2], bhf[p][3]);
                    mma_bf16(acc[f][2 * p + 1], ah[f], blf[p][2], blf[p][3]);
                }
        }
        __syncthreads();
    }

    // Epilogue: write q/k [b,h,n,d] fp32 + BN partial stats
    float* outp = bz ? g_k : g_q;
    const int r0 = m0 + wm + (lane >> 2);
    const int c0 = n0 + wn + (lane & 3) * 2;
    float s1 = 0.f, s2 = 0.f;
#pragma unroll
    for (int f = 0; f < 2; f++)
#pragma unroll
        for (int g = 0; g < 8; g++) {
            int col = c0 + g * 8;
            int h = col >> 6, d = col & 63;
#pragma unroll
            for (int u = 0; u < 2; u++) {
                float v0 = acc[f][g][u * 2], v1 = acc[f][g][u * 2 + 1];
                s1 += v0 + v1;
                s2 += v0 * v0 + v1 * v1;
                int row = r0 + f * 16 + u * 8;
                int bb = row >> 10, nn = row & 1023;
                float* dst = outp + ((size_t)(bb * H_ + h) << 16) + nn * 64 + d;
                *(float2*)dst = make_float2(v0, v1);
            }
        }
#pragma unroll
    for (int o = 16; o; o >>= 1) {
        s1 += __shfl_xor_sync(0xffffffffu, s1, o);
        s2 += __shfl_xor_sync(0xffffffffu, s2, o);
    }
    __shared__ float wsum[8], wsq[8];
    __shared__ int islast;
    if (lane == 0) { wsum[wid] = s1; wsq[wid] = s2; }
    __syncthreads();
    if (tid == 0) {
        int slot = ((bz * 4 + bx) * 64 + by) * 4;
        g_part[slot + 0] = wsum[0] + wsum[1] + wsum[2] + wsum[3];
        g_part[slot + 1] = wsq[0] + wsq[1] + wsq[2] + wsq[3];
        g_part[slot + 2] = wsum[4] + wsum[5] + wsum[6] + wsum[7];
        g_part[slot + 3] = wsq[4] + wsq[5] + wsq[6] + wsq[7];
        __threadfence();
        islast = (atomicAdd(&g_ticket, 1) == 511);
    }
    __syncthreads();
    if (islast) {
        __threadfence();
        if (tid < 16) {
            int t = tid >> 3, h = tid & 7;
            int bx2 = h >> 1, sel = h & 1;
            float a = 0.f, c2 = 0.f;
            for (int by2 = 0; by2 < 64; by2++) {
                int slot = ((t * 4 + bx2) * 64 + by2) * 4 + sel * 2;
                a += g_part[slot];
                c2 += g_part[slot + 1];
            }
            float mean = a * (1.f / (float)HEAD_ELEMS_);
            float var = c2 * (1.f / (float)HEAD_ELEMS_) - mean * mean;
            g_stats[tid * 2] = mean;
            g_stats[tid * 2 + 1] = rsqrtf(var + 1e-5f);
        }
        if (tid == 0) g_ticket = 0;
    }
}

// ---------------------------------------------------------------------------
// Kernel 2: BN + L2 normalize; emit bf16 hi/lo split.
// ---------------------------------------------------------------------------
__global__ void __launch_bounds__(256) normalize_kernel(const float* __restrict__ bnw,
                                                        const float* __restrict__ bnb) {
    int gw = (blockIdx.x * blockDim.x + threadIdx.x) >> 5;
    int lane = threadIdx.x & 31;
    int t = gw >> 16;
    int rem = gw & 65535;
    int h = (rem >> 10) & 7;
    const float* p = (t ? g_k : g_q) + (size_t)rem * 64;
    float mean = g_stats[(t * 8 + h) * 2];
    float rstd = g_stats[(t * 8 + h) * 2 + 1];
    float w = bnw[h], bia = bnb[h];
    float2 v = *(const float2*)(p + lane * 2);
    float x0 = (v.x - mean) * rstd * w + bia;
    float x1 = (v.y - mean) * rstd * w + bia;
    float ss = x0 * x0 + x1 * x1;
#pragma unroll
    for (int o = 16; o; o >>= 1) ss += __shfl_xor_sync(0xffffffffu, ss, o);
    float inv = 1.f / fmaxf(sqrtf(ss), 1e-12f);
    x0 *= inv; x1 *= inv;

    __nv_bfloat16 h0 = __float2bfloat16(x0);
    __nv_bfloat16 h1 = __float2bfloat16(x1);
    __nv_bfloat16 l0 = __float2bfloat16(x0 - __bfloat162float(h0));
    __nv_bfloat16 l1 = __float2bfloat16(x1 - __bfloat162float(h1));
    size_t off = (size_t)rem * 64 + lane * 2;
    __nv_bfloat162 hv; hv.x = h0; hv.y = h1;
    __nv_bfloat162 lv; lv.x = l0; lv.y = l1;
    if (t) {
        *(__nv_bfloat162*)(g_kh + off) = hv;
        *(__nv_bfloat162*)(g_kl + off) = lv;
    } else {
        *(__nv_bfloat162*)(g_qh + off) = hv;
        *(__nv_bfloat162*)(g_ql + off) = lv;
    }
}

// ---------------------------------------------------------------------------
// Kernel 4 (R5/R6-proven): scores GEMM via mma.sync bf16 3-pass hi/lo split.
// Per CTA: 128x128 tile of S^T[b,h,m,n]; 8 warps each 32(m) x 64(n).
// ---------------------------------------------------------------------------
#define RS 144
#define SM_A_HI 0
#define SM_A_LO (128 * RS)
#define SM_B_HI (2 * 128 * RS)
#define SM_B_LO (3 * 128 * RS)
#define SM_TOTAL (4 * 128 * RS)  // 73728

__global__ void __launch_bounds__(256) gemm_scores_mma() {
    extern __shared__ char sm4[];
    const int tid = threadIdx.x;
    const int wid = tid >> 5, lane = tid & 31;
    const int bh = blockIdx.z;
    const int m0 = blockIdx.y * 128;
    const int n0 = blockIdx.x * 128;

    {
        const size_t hb = (size_t)bh * 65536;
        const uint4* sAh = (const uint4*)(g_kh + hb + (size_t)m0 * 64);
        const uint4* sAl = (const uint4*)(g_kl + hb + (size_t)m0 * 64);
        const uint4* sBh = (const uint4*)(g_qh + hb + (size_t)n0 * 64);
        const uint4* sBl = (const uint4*)(g_ql + hb + (size_t)n0 * 64);
#pragma unroll
        for (int i = 0; i < 4; i++) {
            int idx = tid + i * 256;
            int row = idx >> 3, c = idx & 7;
            uint32_t so = row * RS + c * 16;
            *(uint4*)(sm4 + SM_A_HI + so) = sAh[idx];
            *(uint4*)(sm4 + SM_A_LO + so) = sAl[idx];
            *(uint4*)(sm4 + SM_B_HI + so) = sBh[idx];
            *(uint4*)(sm4 + SM_B_LO + so) = sBl[idx];
        }
    }
    __syncthreads();

    const uint32_t sb = smem_u32(sm4);
    const int wm = (wid & 3) * 32;
    const int wn = (wid >> 2) * 64;
    const int l07 = lane & 7;
    const int b3 = (lane >> 3) & 1;
    const int b4 = lane >> 4;
    const uint32_t aOff = (uint32_t)(wm + b3 * 8 + l07) * RS + b4 * 16;
    const uint32_t bOff = (uint32_t)(wn + b4 * 8 + l07) * RS + b3 * 16;

    float acc[2][8][4];
#pragma unroll
    for (int f = 0; f < 2; f++)
#pragma unroll
        for (int g = 0; g < 8; g++)
#pragma unroll
            for (int j = 0; j < 4; j++) acc[f][g][j] = 0.f;

#pragma unroll
    for (int ks = 0; ks < 4; ks++) {
        uint32_t ah[2][4], al[2][4];
#pragma unroll
        for (int f = 0; f < 2; f++) {
            ldsm_x4(ah[f], sb + SM_A_HI + aOff + f * (16 * RS) + ks * 32);
            ldsm_x4(al[f], sb + SM_A_LO + aOff + f * (16 * RS) + ks * 32);
        }
        uint32_t bhf[4][4], blf[4][4];
#pragma unroll
        for (int p = 0; p < 4; p++) {
            ldsm_x4(bhf[p], sb + SM_B_HI + bOff + p * (16 * RS) + ks * 32);
            ldsm_x4(blf[p], sb + SM_B_LO + bOff + p * (16 * RS) + ks * 32);
        }
#pragma unroll
        for (int f = 0; f < 2; f++)
#pragma unroll
            for (int p = 0; p < 4; p++) {
                mma_bf16(acc[f][2 * p],     ah[f], bhf[p][0], bhf[p][1]);
                mma_bf16(acc[f][2 * p],     al[f], bhf[p][0], bhf[p][1]);
                mma_bf16(acc[f][2 * p],     ah[f], blf[p][0], blf[p][1]);
                mma_bf16(acc[f][2 * p + 1], ah[f], bhf[p][2], bhf[p][3]);
                mma_bf16(acc[f][2 * p + 1], al[f], bhf[p][2], bhf[p][3]);
                mma_bf16(acc[f][2 * p + 1], ah[f], blf[p][2], blf[p][3]);
            }
    }

    float* Cp = g_scores + (size_t)bh * 1048576;
    const int r0 = m0 + wm + (lane >> 2);
    const int c0 = n0 + wn + (lane & 3) * 2;
#pragma unroll
    for (int f = 0; f < 2; f++)
#pragma unroll
        for (int g = 0; g < 8; g++) {
            float* d0 = Cp + (size_t)(r0 + f * 16) * 1024 + c0 + g * 8;
            *(float2*)d0 = make_float2(acc[f][g][0] * SCALE_, acc[f][g][1] * SCALE_);
            *(float2*)(d0 + 8 * 1024) = make_float2(acc[f][g][2] * SCALE_, acc[f][g][3] * SCALE_);
        }
}

// ---------------------------------------------------------------------------
// Kernel 5 (R1-proven): sparsemax along n per (b,h,m), transposed output.
// ---------------------------------------------------------------------------
__global__ void __launch_bounds__(1024) sparsemax_kernel(float* __restrict__ out) {
    __shared__ float tile[128][33];
    const int bid = blockIdx.x;
    const int bh = bid >> 5;
    const int mblk = bid & 31;
    const int b = bh >> 3, h = bh & 7;
    const int w = threadIdx.x >> 5, lane = threadIdx.x & 31;
    const int m = mblk * 32 + w;
    const float* row = g_scores + (size_t)bh * 1048576 + (size_t)m * 1024;

    float z[32];
#pragma unroll
    for (int j = 0; j < 32; j++) z[j] = row[j * 32 + lane];

    float mx = z[0];
#pragma unroll
    for (int j = 1; j < 32; j++) mx = fmaxf(mx, z[j]);
#pragma unroll
    for (int o = 16; o; o >>= 1) mx = fmaxf(mx, __shfl_xor_sync(0xffffffffu, mx, o));
#pragma unroll
    for (int j = 0; j < 32; j++) z[j] -= mx;

    float s = 0.f;
#pragma unroll
    for (int j = 0; j < 32; j++) s += z[j];
#pragma unroll
    for (int o = 16; o; o >>= 1) s += __shfl_xor_sync(0xffffffffu, s, o);

    float tau = (s - 1.f) * (1.f / 1024.f);
    int cprev = 1024;
    for (int it = 0; it < 64; it++) {
        float ls = 0.f;
        int lc = 0;
#pragma unroll
        for (int j = 0; j < 32; j++)
            if (z[j] > tau) { ls += z[j]; lc++; }
#pragma unroll
        for (int o = 16; o; o >>= 1) {
            ls += __shfl_xor_sync(0xffffffffu, ls, o);
            lc += __shfl_xor_sync(0xffffffffu, lc, o);
        }
        tau = (ls - 1.f) / (float)lc;
        if (lc == cprev) break;
        cprev = lc;
    }

#pragma unroll
    for (int j = 0; j < 32; j++) z[j] = fmaxf(z[j] - tau, 0.f);

    const size_t outbase = (size_t)b * ((size_t)N_ * 8192) + (size_t)h * 1024 + mblk * 32;
#pragma unroll 1
    for (int g = 0; g < 8; g++) {
#pragma unroll
        for (int q = 0; q < 4; q++) tile[q * 32 + lane][w] = z[g * 4 + q];
        __syncthreads();
#pragma unroll
        for (int k = 0; k < 4; k++) {
            int flat = threadIdx.x + k * 1024;
            int nl = flat >> 5, ml = flat & 31;
            out[outbase + (size_t)(g * 128 + nl) * 8192 + ml] = tile[nl][ml];
        }
        __syncthreads();
    }
}

// ---------------------------------------------------------------------------
extern "C" void kernel_launch(void* const* d_in, const int* in_sizes, int n_in,
                              void* d_out, int out_size) {
    (void)in_sizes; (void)n_in; (void)out_size;
    const float* x   = (const float*)d_in[0];
    const float* qw  = (const float*)d_in[1];
    const float* kw  = (const float*)d_in[2];
    const float* bnw = (const float*)d_in[3];
    const float* bnb = (const float*)d_in[4];
    float* out = (float*)d_out;

    cudaFuncSetAttribute(gemm_qk_mma,
                         cudaFuncAttributeMaxDynamicSharedMemorySize, QK_SMEM);
    cudaFuncSetAttribute(gemm_scores_mma,
                         cudaFuncAttributeMaxDynamicSharedMemorySize, SM_TOTAL);

    split_inputs_kernel<<<2304, 256>>>(x, qw, kw);
    dim3 g1(4, 64, 2);
    gemm_qk_mma<<<g1, 256, QK_SMEM>>>();
    normalize_kernel<<<16384, 256>>>(bnw, bnb);
    dim3 g2(8, 8, 64);
    gemm_scores_mma<<<g2, 256, SM_TOTAL>>>();
    sparsemax_kernel<<<2048, 1024>>>(out);
}

// round 12
// speedup vs baseline: 1.0501x; 1.0501x over previous
#include <cuda_runtime.h>
#include <cuda_bf16.h>
#include <cstdint>

// Problem constants
#define B_  8
#define N_  1024
#define C_  256
#define H_  8
#define BH_ (B_ * H_)
#define HEAD_ELEMS_ 524288
#define SCALE_ 0.0625f

// Scratch (device globals)
__device__ float g_q[BH_ * N_ * 64];
__device__ float g_k[BH_ * N_ * 64];
__device__ float g_part[2048];
__device__ float g_stats[16 * 2];
__device__ int   g_ticket;
__device__ __nv_bfloat16 g_qh[BH_ * N_ * 64];
__device__ __nv_bfloat16 g_ql[BH_ * N_ * 64];
__device__ __nv_bfloat16 g_kh[BH_ * N_ * 64];
__device__ __nv_bfloat16 g_kl[BH_ * N_ * 64];
__device__ __nv_bfloat16 g_xh[8192 * 256];
__device__ __nv_bfloat16 g_xl[8192 * 256];
__device__ __nv_bfloat16 g_wh[1024 * 256];
__device__ __nv_bfloat16 g_wl[1024 * 256];

// ---------------------------------------------------------------------------
// helpers
// ---------------------------------------------------------------------------
__device__ __forceinline__ uint32_t smem_u32(const void* p) {
    uint32_t a;
    asm("{ .reg .u64 t; cvta.to.shared.u64 t, %1; cvt.u32.u64 %0, t; }" : "=r"(a) : "l"(p));
    return a;
}
__device__ __forceinline__ void ldsm_x4(uint32_t* r, uint32_t addr) {
    asm volatile("ldmatrix.sync.aligned.m8n8.x4.shared.b16 {%0,%1,%2,%3}, [%4];"
                 : "=r"(r[0]), "=r"(r[1]), "=r"(r[2]), "=r"(r[3]) : "r"(addr));
}
__device__ __forceinline__ void mma_bf16(float* c, const uint32_t* a, uint32_t b0, uint32_t b1) {
    asm volatile("mma.sync.aligned.m16n8k16.row.col.f32.bf16.bf16.f32 "
                 "{%0,%1,%2,%3},{%4,%5,%6,%7},{%8,%9},{%0,%1,%2,%3};"
                 : "+f"(c[0]), "+f"(c[1]), "+f"(c[2]), "+f"(c[3])
                 : "r"(a[0]), "r"(a[1]), "r"(a[2]), "r"(a[3]), "r"(b0), "r"(b1));
}
__device__ __forceinline__ void cp16(uint32_t d, const void* s) {
    asm volatile("cp.async.cg.shared.global [%0], [%1], 16;" :: "r"(d), "l"(s));
}
#define CP_COMMIT() asm volatile("cp.async.commit_group;" ::: "memory")
#define CP_WAIT1()  asm volatile("cp.async.wait_group 1;" ::: "memory")
#define CP_WAIT0()  asm volatile("cp.async.wait_group 0;" ::: "memory")

// ---------------------------------------------------------------------------
// Kernel 0: bf16 hi/lo split of x and [qw;kw]
// ---------------------------------------------------------------------------
__global__ void __launch_bounds__(256) split_inputs_kernel(const float* __restrict__ x,
                                                           const float* __restrict__ qw,
                                                           const float* __restrict__ kw) {
    int idx = (blockIdx.x * 256 + threadIdx.x) * 4;
    const float* src;
    __nv_bfloat16 *dh, *dl;
    int off;
    if (idx < 2097152) {
        src = x; off = idx; dh = g_xh; dl = g_xl;
    } else if (idx < 2097152 + 131072) {
        src = qw; off = idx - 2097152; dh = g_wh; dl = g_wl;
    } else {
        src = kw; off = idx - 2097152 - 131072; dh = g_wh + 131072; dl = g_wl + 131072;
    }
    float4 v = *(const float4*)(src + off);
    __nv_bfloat16 h0 = __float2bfloat16(v.x), h1 = __float2bfloat16(v.y);
    __nv_bfloat16 h2 = __float2bfloat16(v.z), h3 = __float2bfloat16(v.w);
    __nv_bfloat162 hv0, hv1, lv0, lv1;
    hv0.x = h0; hv0.y = h1; hv1.x = h2; hv1.y = h3;
    lv0.x = __float2bfloat16(v.x - __bfloat162float(h0));
    lv0.y = __float2bfloat16(v.y - __bfloat162float(h1));
    lv1.x = __float2bfloat16(v.z - __bfloat162float(h2));
    lv1.y = __float2bfloat16(v.w - __bfloat162float(h3));
    *(__nv_bfloat162*)(dh + off)     = hv0;
    *(__nv_bfloat162*)(dh + off + 2) = hv1;
    *(__nv_bfloat162*)(dl + off)     = lv0;
    *(__nv_bfloat162*)(dl + off + 2) = lv1;
}

// ---------------------------------------------------------------------------
// Kernel 1: q/k = x @ w^T, cp.async 2-stage pipeline (R10-proven).
// Epilogue folds BN partial stats; last CTA (ticket) finalizes g_stats.
// ---------------------------------------------------------------------------
#define QK_STAGE 40960
#define QK_AHI 0
#define QK_ALO 10240
#define QK_BHI 20480
#define QK_BLO 30720
#define QK_SMEM (2 * QK_STAGE)   // 81920

__global__ void __launch_bounds__(256, 2) gemm_qk_mma() {
    extern __shared__ char smq[];
    const uint32_t sb = smem_u32(smq);
    const int tid = threadIdx.x;
    const int wid = tid >> 5, lane = tid & 31;
    const int bx = blockIdx.x, by = blockIdx.y, bz = blockIdx.z;
    const int m0 = by * 128, n0 = bx * 128;
    const __nv_bfloat16* Bh = g_wh + (size_t)(bz * 512) * 256;
    const __nv_bfloat16* Bl = g_wl + (size_t)(bz * 512) * 256;

    auto stage = [&](int kc, int buf) {
        uint32_t base = sb + buf * QK_STAGE;
#pragma unroll
        for (int i = 0; i < 2; i++) {
            int idx = tid + i * 256;
            int row = idx >> 2, c = idx & 3;
            uint32_t so = (uint32_t)row * 80 + c * 16;
            size_t goA = (size_t)(m0 + row) * 256 + kc * 32 + c * 8;
            size_t goB = (size_t)(n0 + row) * 256 + kc * 32 + c * 8;
            cp16(base + QK_AHI + so, g_xh + goA);
            cp16(base + QK_ALO + so, g_xl + goA);
            cp16(base + QK_BHI + so, Bh + goB);
            cp16(base + QK_BLO + so, Bl + goB);
        }
    };

    const int wm = (wid & 3) * 32;
    const int wn = (wid >> 2) * 64;
    const int l07 = lane & 7;
    const int b3 = (lane >> 3) & 1;
    const int b4 = lane >> 4;
    const uint32_t aOff = (uint32_t)(wm + b3 * 8 + l07) * 80 + b4 * 16;
    const uint32_t bOff = (uint32_t)(wn + b4 * 8 + l07) * 80 + b3 * 16;

    float acc[2][8][4];
#pragma unroll
    for (int f = 0; f < 2; f++)
#pragma unroll
        for (int g = 0; g < 8; g++)
#pragma unroll
            for (int j = 0; j < 4; j++) acc[f][g][j] = 0.f;

    stage(0, 0);
    CP_COMMIT();

#pragma unroll 1
    for (int kc = 0; kc < 8; kc++) {
        if (kc < 7) { stage(kc + 1, (kc + 1) & 1); CP_COMMIT(); CP_WAIT1(); }
        else CP_WAIT0();
        __syncthreads();
        uint32_t base = sb + (kc & 1) * QK_STAGE;
#pragma unroll
        for (int ks = 0; ks < 2; ks++) {
            uint32_t ah[2][4], al[2][4];
#pragma unroll
            for (int f = 0; f < 2; f++) {
                ldsm_x4(ah[f], base + QK_AHI + aOff + f * 1280 + ks * 32);
                ldsm_x4(al[f], base + QK_ALO + aOff + f * 1280 + ks * 32);
            }
            uint32_t bhf[4][4], blf[4][4];
#pragma unroll
            for (int p = 0; p < 4; p++) {
                ldsm_x4(bhf[p], base + QK_BHI + bOff + p * 1280 + ks * 32);
                ldsm_x4(blf[p], base + QK_BLO + bOff + p * 1280 + ks * 32);
            }
#pragma unroll
            for (int f = 0; f < 2; f++)
#pragma unroll
                for (int p = 0; p < 4; p++) {
                    mma_bf16(acc[f][2 * p],     ah[f], bhf[p][0], bhf[p][1]);
                    mma_bf16(acc[f][2 * p],     al[f], bhf[p][0], bhf[p][1]);
                    mma_bf16(acc[f][2 * p],     ah[f], blf[p][0], blf[p][1]);
                    mma_bf16(acc[f][2 * p + 1], ah[f], bhf[p][2], bhf[p][3]);
                    mma_bf16(acc[f][2 * p + 1], al[f], bhf[p][2], bhf[p][3]);
                    mma_bf16(acc[f][2 * p + 1], ah[f], blf[p][2], blf[p][3]);
                }
        }
        __syncthreads();
    }

    float* outp = bz ? g_k : g_q;
    const int r0 = m0 + wm + (lane >> 2);
    const int c0 = n0 + wn + (lane & 3) * 2;
    float s1 = 0.f, s2 = 0.f;
#pragma unroll
    for (int f = 0; f < 2; f++)
#pragma unroll
        for (int g = 0; g < 8; g++) {
            int col = c0 + g * 8;
            int h = col >> 6, d = col & 63;
#pragma unroll
            for (int u = 0; u < 2; u++) {
                float v0 = acc[f][g][u * 2], v1 = acc[f][g][u * 2 + 1];
                s1 += v0 + v1;
                s2 += v0 * v0 + v1 * v1;
                int row = r0 + f * 16 + u * 8;
                int bb = row >> 10, nn = row & 1023;
                float* dst = outp + ((size_t)(bb * H_ + h) << 16) + nn * 64 + d;
                *(float2*)dst = make_float2(v0, v1);
            }
        }
#pragma unroll
    for (int o = 16; o; o >>= 1) {
        s1 += __shfl_xor_sync(0xffffffffu, s1, o);
        s2 += __shfl_xor_sync(0xffffffffu, s2, o);
    }
    __shared__ float wsum[8], wsq[8];
    __shared__ int islast;
    if (lane == 0) { wsum[wid] = s1; wsq[wid] = s2; }
    __syncthreads();
    if (tid == 0) {
        int slot = ((bz * 4 + bx) * 64 + by) * 4;
        g_part[slot + 0] = wsum[0] + wsum[1] + wsum[2] + wsum[3];
        g_part[slot + 1] = wsq[0] + wsq[1] + wsq[2] + wsq[3];
        g_part[slot + 2] = wsum[4] + wsum[5] + wsum[6] + wsum[7];
        g_part[slot + 3] = wsq[4] + wsq[5] + wsq[6] + wsq[7];
        __threadfence();
        islast = (atomicAdd(&g_ticket, 1) == 511);
    }
    __syncthreads();
    if (islast) {
        __threadfence();
        if (tid < 16) {
            int t = tid >> 3, h = tid & 7;
            int bx2 = h >> 1, sel = h & 1;
            float a = 0.f, c2 = 0.f;
            for (int by2 = 0; by2 < 64; by2++) {
                int slot = ((t * 4 + bx2) * 64 + by2) * 4 + sel * 2;
                a += g_part[slot];
                c2 += g_part[slot + 1];
            }
            float mean = a * (1.f / (float)HEAD_ELEMS_);
            float var = c2 * (1.f / (float)HEAD_ELEMS_) - mean * mean;
            g_stats[tid * 2] = mean;
            g_stats[tid * 2 + 1] = rsqrtf(var + 1e-5f);
        }
        if (tid == 0) g_ticket = 0;
    }
}

// ---------------------------------------------------------------------------
// Kernel 2: BN + L2 normalize; emit bf16 hi/lo split.
// ---------------------------------------------------------------------------
__global__ void __launch_bounds__(256) normalize_kernel(const float* __restrict__ bnw,
                                                        const float* __restrict__ bnb) {
    int gw = (blockIdx.x * blockDim.x + threadIdx.x) >> 5;
    int lane = threadIdx.x & 31;
    int t = gw >> 16;
    int rem = gw & 65535;
    int h = (rem >> 10) & 7;
    const float* p = (t ? g_k : g_q) + (size_t)rem * 64;
    float mean = g_stats[(t * 8 + h) * 2];
    float rstd = g_stats[(t * 8 + h) * 2 + 1];
    float w = bnw[h], bia = bnb[h];
    float2 v = *(const float2*)(p + lane * 2);
    float x0 = (v.x - mean) * rstd * w + bia;
    float x1 = (v.y - mean) * rstd * w + bia;
    float ss = x0 * x0 + x1 * x1;
#pragma unroll
    for (int o = 16; o; o >>= 1) ss += __shfl_xor_sync(0xffffffffu, ss, o);
    float inv = 1.f / fmaxf(sqrtf(ss), 1e-12f);
    x0 *= inv; x1 *= inv;

    __nv_bfloat16 h0 = __float2bfloat16(x0);
    __nv_bfloat16 h1 = __float2bfloat16(x1);
    __nv_bfloat16 l0 = __float2bfloat16(x0 - __bfloat162float(h0));
    __nv_bfloat16 l1 = __float2bfloat16(x1 - __bfloat162float(h1));
    size_t off = (size_t)rem * 64 + lane * 2;
    __nv_bfloat162 hv; hv.x = h0; hv.y = h1;
    __nv_bfloat162 lv; lv.x = l0; lv.y = l1;
    if (t) {
        *(__nv_bfloat162*)(g_kh + off) = hv;
        *(__nv_bfloat162*)(g_kl + off) = lv;
    } else {
        *(__nv_bfloat162*)(g_qh + off) = hv;
        *(__nv_bfloat162*)(g_ql + off) = lv;
    }
}

// ---------------------------------------------------------------------------
// Kernel 3 (fused v3): scores 32x1024 per CTA, acc stays IN REGISTERS.
// Q staged via cp.async double buffer + ldmatrix; sparsemax via in-register
// predicated reductions + 32x8 smem combine per iteration (no score slab).
// Output written directly from registers (full 32B sectors).
// ---------------------------------------------------------------------------
#define FS_K_HI 0
#define FS_K_LO 4608
#define FS_Q    9216
#define FS_QSTG 18432
#define FS_PART (FS_Q + 4 * FS_QSTG)       // 82944: float[32][8]
#define FS_CNT  (FS_PART + 1024)           // int[32][8]
#define FS_TAUS (FS_CNT + 1024)            // float[32]
#define FS_CPRV (FS_TAUS + 128)            // int[32]
#define FS_FLAG (FS_CPRV + 128)            // int[2]
#define FS_SMEM (FS_FLAG + 128)            // ~85.5 KB

__global__ void __launch_bounds__(512, 1) fused_scores_sparsemax(float* __restrict__ out) {
    extern __shared__ char smf[];
    const uint32_t sb = smem_u32(smf);
    float* partS = (float*)(smf + FS_PART);
    int*   cntS  = (int*)(smf + FS_CNT);
    float* tauS  = (float*)(smf + FS_TAUS);
    int*   cprvS = (int*)(smf + FS_CPRV);
    int*   flagS = (int*)(smf + FS_FLAG);

    const int tid = threadIdx.x;
    const int w = tid >> 5, lane = tid & 31;
    const int wm = w & 1, wn = w >> 1;           // row-half, col-group
    const int bh = blockIdx.y;
    const int m0 = blockIdx.x * 32;
    const size_t hbase = (size_t)bh * 65536;

    auto stageQ = [&](int c, int buf) {
        uint32_t qb = sb + FS_Q + buf * 2 * FS_QSTG;
#pragma unroll
        for (int i = 0; i < 2; i++) {
            int idx = tid + i * 512;
            int row = idx >> 3, cc = idx & 7;
            size_t go = hbase + (size_t)(c * 128 + row) * 64 + cc * 8;
            uint32_t so = (uint32_t)row * 144 + cc * 16;
            cp16(qb + so, g_qh + go);
            cp16(qb + FS_QSTG + so, g_ql + go);
        }
    };

    // Stage K tile [32 x 64] hi+lo (plain stores)
    {
        int half = tid >> 8, idx = tid & 255;
        int row = idx >> 3, c = idx & 7;
        const __nv_bfloat16* src = (half ? g_kl : g_kh) + hbase + (size_t)(m0 + row) * 64 + c * 8;
        *(uint4*)(smf + (half ? FS_K_LO : FS_K_HI) + row * 144 + c * 16) = *(const uint4*)src;
    }
    stageQ(0, 0);
    CP_COMMIT();
    __syncthreads();

    // Preload A fragments (K tile): warp's rows = wm*16 .. +15
    const int l07 = lane & 7;
    const int b3 = (lane >> 3) & 1;
    const int b4 = lane >> 4;
    const uint32_t aOff = (uint32_t)(wm * 16 + b3 * 8 + l07) * 144 + b4 * 16;
    uint32_t ah[4][4], al[4][4];
#pragma unroll
    for (int ks = 0; ks < 4; ks++) {
        ldsm_x4(ah[ks], sb + FS_K_HI + aOff + ks * 32);
        ldsm_x4(al[ks], sb + FS_K_LO + aOff + ks * 32);
    }

    const uint32_t bOff = (uint32_t)(wn * 16 + b4 * 8 + l07) * 144 + b3 * 16;
    float acc[8][2][4];
#pragma unroll
    for (int c = 0; c < 8; c++)
#pragma unroll
        for (int nf = 0; nf < 2; nf++)
#pragma unroll
            for (int j = 0; j < 4; j++) acc[c][nf][j] = 0.f;

#pragma unroll 1
    for (int c = 0; c < 8; c++) {
        if (c < 7) { stageQ(c + 1, (c + 1) & 1); CP_COMMIT(); CP_WAIT1(); }
        else CP_WAIT0();
        __syncthreads();
        uint32_t qb = sb + FS_Q + (c & 1) * 2 * FS_QSTG;
#pragma unroll
        for (int ks = 0; ks < 4; ks++) {
            uint32_t bhf[4], blf[4];
            ldsm_x4(bhf, qb + bOff + ks * 32);
            ldsm_x4(blf, qb + FS_QSTG + bOff + ks * 32);
#pragma unroll
            for (int nf = 0; nf < 2; nf++) {
                mma_bf16(acc[c][nf], ah[ks], bhf[2 * nf], bhf[2 * nf + 1]);
                mma_bf16(acc[c][nf], al[ks], bhf[2 * nf], bhf[2 * nf + 1]);
                mma_bf16(acc[c][nf], ah[ks], blf[2 * nf], blf[2 * nf + 1]);
            }
        }
        __syncthreads();   // readers done before next stageQ overwrites
    }

    // Scale in place
#pragma unroll
    for (int c = 0; c < 8; c++)
#pragma unroll
        for (int nf = 0; nf < 2; nf++)
#pragma unroll
            for (int j = 0; j < 4; j++) acc[c][nf][j] *= SCALE_;

    // Per-lane row assignment: r0 = wm*16 + (lane>>2), r1 = r0 + 8.
    const int lq = lane & 3;
    const int r0 = wm * 16 + (lane >> 2);
    const int r1 = r0 + 8;

    // Initial full sums per row
    {
        float s0 = 0.f, s1 = 0.f;
#pragma unroll
        for (int c = 0; c < 8; c++)
#pragma unroll
            for (int nf = 0; nf < 2; nf++) {
                s0 += acc[c][nf][0] + acc[c][nf][1];
                s1 += acc[c][nf][2] + acc[c][nf][3];
            }
        s0 += __shfl_xor_sync(0xffffffffu, s0, 1);
        s0 += __shfl_xor_sync(0xffffffffu, s0, 2);
        s1 += __shfl_xor_sync(0xffffffffu, s1, 1);
        s1 += __shfl_xor_sync(0xffffffffu, s1, 2);
        if (lq == 0) { partS[r0 * 8 + wn] = s0; partS[r1 * 8 + wn] = s1; }
    }
    if (tid == 0) { flagS[0] = 0; flagS[1] = 0; }
    __syncthreads();
    {
        int row = 2 * w + ((lane >> 3) & 1);
        float v = partS[row * 8 + (lane & 7)];
        v += __shfl_xor_sync(0xffffffffu, v, 1);
        v += __shfl_xor_sync(0xffffffffu, v, 2);
        v += __shfl_xor_sync(0xffffffffu, v, 4);
        if ((lane & 7) == 0 && lane < 16) {
            tauS[row] = (v - 1.f) * (1.f / 1024.f);
            cprvS[row] = 1024;
        }
    }
    __syncthreads();

    // Michelot fixed point (exact; terminates when active set stable)
#pragma unroll 1
    for (int it = 0; it < 64; it++) {
        float t0 = tauS[r0], t1 = tauS[r1];
        float s0 = 0.f, s1 = 0.f;
        int n0 = 0, n1 = 0;
#pragma unroll
        for (int c = 0; c < 8; c++)
#pragma unroll
            for (int nf = 0; nf < 2; nf++) {
                float v;
                v = acc[c][nf][0]; if (v > t0) { s0 += v; n0++; }
                v = acc[c][nf][1]; if (v > t0) { s0 += v; n0++; }
                v = acc[c][nf][2]; if (v > t1) { s1 += v; n1++; }
                v = acc[c][nf][3]; if (v > t1) { s1 += v; n1++; }
            }
        s0 += __shfl_xor_sync(0xffffffffu, s0, 1);
        s0 += __shfl_xor_sync(0xffffffffu, s0, 2);
        n0 += __shfl_xor_sync(0xffffffffu, n0, 1);
        n0 += __shfl_xor_sync(0xffffffffu, n0, 2);
        s1 += __shfl_xor_sync(0xffffffffu, s1, 1);
        s1 += __shfl_xor_sync(0xffffffffu, s1, 2);
        n1 += __shfl_xor_sync(0xffffffffu, n1, 1);
        n1 += __shfl_xor_sync(0xffffffffu, n1, 2);
        if (lq == 0) {
            partS[r0 * 8 + wn] = s0; cntS[r0 * 8 + wn] = n0;
            partS[r1 * 8 + wn] = s1; cntS[r1 * 8 + wn] = n1;
        }
        if (tid == 0) flagS[(it + 1) & 1] = 0;
        __syncthreads();

        int row = 2 * w + ((lane >> 3) & 1);
        float v = partS[row * 8 + (lane & 7)];
        int cc = cntS[row * 8 + (lane & 7)];
        v += __shfl_xor_sync(0xffffffffu, v, 1);
        v += __shfl_xor_sync(0xffffffffu, v, 2);
        v += __shfl_xor_sync(0xffffffffu, v, 4);
        cc += __shfl_xor_sync(0xffffffffu, cc, 1);
        cc += __shfl_xor_sync(0xffffffffu, cc, 2);
        cc += __shfl_xor_sync(0xffffffffu, cc, 4);
        if ((lane & 7) == 0 && lane < 16) {
            tauS[row] = (v - 1.f) / (float)cc;
            if (cc != cprvS[row]) { cprvS[row] = cc; flagS[it & 1] = 1; }
        }
        __syncthreads();
        if (flagS[it & 1] == 0) break;
    }

    // Direct transposed output from registers: out[b, n, h*1024 + m0 + r]
    const int b = bh >> 3, h = bh & 7;
    const float t0 = tauS[r0], t1 = tauS[r1];
    const size_t ob = (size_t)b * 8388608 + (size_t)h * 1024 + m0;
#pragma unroll
    for (int c = 0; c < 8; c++)
#pragma unroll
        for (int nf = 0; nf < 2; nf++) {
            int n = c * 128 + wn * 16 + nf * 8 + lq * 2;
            out[ob + (size_t)n * 8192 + r0]       = fmaxf(acc[c][nf][0] - t0, 0.f);
            out[ob + (size_t)(n + 1) * 8192 + r0] = fmaxf(acc[c][nf][1] - t0, 0.f);
            out[ob + (size_t)n * 8192 + r1]       = fmaxf(acc[c][nf][2] - t1, 0.f);
            out[ob + (size_t)(n + 1) * 8192 + r1] = fmaxf(acc[c][nf][3] - t1, 0.f);
        }
}

// ---------------------------------------------------------------------------
extern "C" void kernel_launch(void* const* d_in, const int* in_sizes, int n_in,
                              void* d_out, int out_size) {
    (void)in_sizes; (void)n_in; (void)out_size;
    const float* x   = (const float*)d_in[0];
    const float* qw  = (const float*)d_in[1];
    const float* kw  = (const float*)d_in[2];
    const float* bnw = (const float*)d_in[3];
    const float* bnb = (const float*)d_in[4];
    float* out = (float*)d_out;

    cudaFuncSetAttribute(gemm_qk_mma,
                         cudaFuncAttributeMaxDynamicSharedMemorySize, QK_SMEM);
    cudaFuncSetAttribute(fused_scores_sparsemax,
                         cudaFuncAttributeMaxDynamicSharedMemorySize, FS_SMEM);

    split_inputs_kernel<<<2304, 256>>>(x, qw, kw);
    dim3 g1(4, 64, 2);
    gemm_qk_mma<<<g1, 256, QK_SMEM>>>();
    normalize_kernel<<<16384, 256>>>(bnw, bnb);
    dim3 g2(32, 64);
    fused_scores_sparsemax<<<g2, 512, FS_SMEM>>>(out);
}